// round 3
// baseline (speedup 1.0000x reference)
#include <cuda_runtime.h>

// Problem constants
#define S_DIM 8
#define D_DIM 2048
#define N_DIM 1024
#define B_DIM 2
#define SD    16384          // S*D
#define NJ    22             // 14 alpha cols + 8 beta cols
#define NACC  23             // + sumsq
#define BN    2048           // B*N
#define KSPL  8              // k-split == s

typedef unsigned long long ull;

// Scratch (static __device__ arrays; no allocation)
__device__ __align__(16) float g_Wt[NJ * SD];        // Wt[j][k] = (gamma[k]+1)*W[k][j]
__device__ float g_part[KSPL][BN][NACC];             // per-split partial reductions
__device__ float g_M[BN * 64];                       // per-(b,n) 8x8 mixing matrix

__device__ __forceinline__ void fma2(ull &acc, ull a, ull b) {
    asm("fma.rn.f32x2 %0, %1, %2, %3;" : "=l"(acc) : "l"(a), "l"(b), "l"(acc));
}
__device__ __forceinline__ float f2sum(ull v) {
    float2 f = *reinterpret_cast<float2*>(&v);
    return f.x + f.y;
}
__device__ __forceinline__ float wsum(float v) {
    #pragma unroll
    for (int o = 16; o > 0; o >>= 1) v += __shfl_down_sync(0xffffffffu, v, o);
    return v;
}

// ---------------------------------------------------------------------------
// Kernel P: build Wt[j][k] = (gamma[k]+1) * W[k][j]  (transposed, gamma-folded)
// ---------------------------------------------------------------------------
__global__ void k_prep(const float* __restrict__ gamma,
                       const float* __restrict__ Wa,
                       const float* __restrict__ Wb) {
    int i = blockIdx.x * blockDim.x + threadIdx.x;
    if (i >= NJ * SD) return;
    int j = i >> 14;          // / 16384
    int k = i & (SD - 1);
    float g = gamma[k] + 1.0f;
    float w = (j < 14) ? Wa[k * 14 + j] : Wb[k * 8 + (j - 14)];
    g_Wt[j * SD + k] = g * w;
}

// ---------------------------------------------------------------------------
// Kernel A: reductions. grid=(BN/16, 8). Each warp owns 2 bn values and scans
// the k-slice for s=blockIdx.y (2048 contiguous floats of each residual row).
// f32x2 FMAs, LDG.128 for both residuals and Wt.
// ---------------------------------------------------------------------------
__global__ __launch_bounds__(256) void k_reduce(const float* __restrict__ resid) {
    const int warp  = threadIdx.x >> 5;
    const int lane  = threadIdx.x & 31;
    const int split = blockIdx.y;                 // == s
    const int bn0   = blockIdx.x * 16 + warp * 2;
    const int bn1   = bn0 + 1;
    const int b0 = bn0 >> 10, n0 = bn0 & 1023;
    const int b1 = bn1 >> 10, n1 = bn1 & 1023;

    // pointers in ulonglong2 (16B) units
    const ulonglong2* r0 = reinterpret_cast<const ulonglong2*>(resid)
        + (size_t)b0 * 4194304u + (size_t)split * 524288u + (size_t)n0 * 512u;
    const ulonglong2* r1 = reinterpret_cast<const ulonglong2*>(resid)
        + (size_t)b1 * 4194304u + (size_t)split * 524288u + (size_t)n1 * 512u;
    const ulonglong2* wt = reinterpret_cast<const ulonglong2*>(g_Wt)
        + (size_t)split * 512u;

    ull acc0[NACC], acc1[NACC];
    #pragma unroll
    for (int j = 0; j < NACC; j++) { acc0[j] = 0ull; acc1[j] = 0ull; }

    int idx = lane;
    for (int it = 0; it < 16; ++it, idx += 32) {
        ulonglong2 ra = r0[idx];
        ulonglong2 rb = r1[idx];
        fma2(acc0[22], ra.x, ra.x); fma2(acc0[22], ra.y, ra.y);
        fma2(acc1[22], rb.x, rb.x); fma2(acc1[22], rb.y, rb.y);
        #pragma unroll
        for (int j = 0; j < NJ; j++) {
            ulonglong2 w = wt[j * 4096 + idx];
            fma2(acc0[j], ra.x, w.x); fma2(acc0[j], ra.y, w.y);
            fma2(acc1[j], rb.x, w.x); fma2(acc1[j], rb.y, w.y);
        }
    }

    #pragma unroll
    for (int j = 0; j < NACC; j++) {
        float v0 = wsum(f2sum(acc0[j]));
        float v1 = wsum(f2sum(acc1[j]));
        if (lane == 0) {
            g_part[split][bn0][j] = v0;
            g_part[split][bn1][j] = v1;
        }
    }
}

// ---------------------------------------------------------------------------
// Kernel B: per-(b,n) scalar epilogue -> 8x8 mixing matrix M
// ---------------------------------------------------------------------------
__global__ void k_mix(const float* __restrict__ salpha,
                      const float* __restrict__ pbs,
                      const float* __restrict__ rscale,
                      const float* __restrict__ sbeta,
                      const float* __restrict__ hps) {
    int bn = blockIdx.x * blockDim.x + threadIdx.x;
    if (bn >= BN) return;

    float dot[NACC];
    #pragma unroll
    for (int j = 0; j < NACC; j++) {
        float v = 0.0f;
        #pragma unroll
        for (int sp = 0; sp < KSPL; sp++) v += g_part[sp][bn][j];
        dot[j] = v;
    }

    // normed = flat * inv * sqrt(SD) * (gamma+1); gamma folded into Wt already
    float scale = rsqrtf(fmaxf(dot[22], 1e-24f)) * 128.0f;  // sqrt(16384)=128
    float ps = pbs[0], rs = rscale[0], hp = hps[0];

    // w_pre = softmax(ps * dyn_pre + static_alpha[:8])
    float l[8], mx = -1e30f;
    #pragma unroll
    for (int i = 0; i < 8; i++) {
        l[i] = ps * (scale * dot[i]) + salpha[i];
        mx = fmaxf(mx, l[i]);
    }
    float e[8], sum = 0.0f;
    #pragma unroll
    for (int i = 0; i < 8; i++) { e[i] = expf(l[i] - mx); sum += e[i]; }
    float inv_sum = 1.0f / sum;
    float wpre[8];
    #pragma unroll
    for (int i = 0; i < 8; i++) wpre[i] = e[i] * inv_sum;

    // p_k = softmax over pairs -> first element
    float p[3];
    #pragma unroll
    for (int k = 0; k < 3; k++) {
        float c0 = rs * (scale * dot[8 + 2 * k])     + salpha[8 + 2 * k];
        float c1 = rs * (scale * dot[8 + 2 * k + 1]) + salpha[8 + 2 * k + 1];
        p[k] = 1.0f / (1.0f + expf(c1 - c0));
    }
    // Kron structure: H[s][t] = h[s^t], bit2<-k0, bit1<-k1, bit0<-k2
    float h[8];
    #pragma unroll
    for (int x = 0; x < 8; x++) {
        float f0 = (x & 4) ? (1.0f - p[0]) : p[0];
        float f1 = (x & 2) ? (1.0f - p[1]) : p[1];
        float f2 = (x & 1) ? (1.0f - p[2]) : p[2];
        h[x] = f0 * f1 * f2;
    }
    float beta[8];
    #pragma unroll
    for (int t = 0; t < 8; t++)
        beta[t] = 1.0f / (1.0f + expf(-(hp * (scale * dot[14 + t]) + sbeta[t])));

    float* Mo = &g_M[bn * 64];
    #pragma unroll
    for (int s = 0; s < 8; s++)
        #pragma unroll
        for (int t = 0; t < 8; t++)
            Mo[s * 8 + t] = h[s ^ t] + beta[t] * wpre[s];
}

// ---------------------------------------------------------------------------
// Kernel C: out[t,d] = sum_s M[s][t] * r[s,d].  One CTA per (b,n).
// ---------------------------------------------------------------------------
__global__ __launch_bounds__(256) void k_apply(const float* __restrict__ resid,
                                               float* __restrict__ out) {
    const int bn = blockIdx.x;
    const int b = bn >> 10, n = bn & 1023;

    __shared__ float Ms[64];
    if (threadIdx.x < 64) Ms[threadIdx.x] = g_M[bn * 64 + threadIdx.x];
    __syncthreads();

    float M[64];
    #pragma unroll
    for (int i = 0; i < 64; i++) M[i] = Ms[i];

    const size_t base = (size_t)b * 16777216u + (size_t)n * 2048u;

    #pragma unroll
    for (int pass = 0; pass < 2; pass++) {
        const int d = pass * 1024 + threadIdx.x * 4;
        float4 acc[8];
        #pragma unroll
        for (int t = 0; t < 8; t++) acc[t] = make_float4(0.f, 0.f, 0.f, 0.f);

        #pragma unroll
        for (int s = 0; s < 8; s++) {
            float4 r4 = *reinterpret_cast<const float4*>(resid + base + (size_t)s * 2097152u + d);
            #pragma unroll
            for (int t = 0; t < 8; t++) {
                float m = M[s * 8 + t];
                acc[t].x += m * r4.x;
                acc[t].y += m * r4.y;
                acc[t].z += m * r4.z;
                acc[t].w += m * r4.w;
            }
        }
        #pragma unroll
        for (int t = 0; t < 8; t++)
            *reinterpret_cast<float4*>(out + base + (size_t)t * 2097152u + d) = acc[t];
    }
}

// ---------------------------------------------------------------------------
extern "C" void kernel_launch(void* const* d_in, const int* in_sizes, int n_in,
                              void* d_out, int out_size) {
    const float* resid  = (const float*)d_in[0];   // residuals (B*S, N, D)
    const float* gamma  = (const float*)d_in[1];   // (S*D,)
    const float* salpha = (const float*)d_in[2];   // (S+T,) = 14
    const float* Wa     = (const float*)d_in[3];   // (S*D, 14)
    const float* pbs    = (const float*)d_in[4];   // (1,)
    const float* rs     = (const float*)d_in[5];   // (1,)
    const float* sbeta  = (const float*)d_in[6];   // (S,) = 8
    const float* Wb     = (const float*)d_in[7];   // (S*D, 8)
    const float* hps    = (const float*)d_in[8];   // scalar
    float* out = (float*)d_out;

    k_prep<<<(NJ * SD + 255) / 256, 256>>>(gamma, Wa, Wb);
    k_reduce<<<dim3(BN / 16, KSPL), 256>>>(resid);
    k_mix<<<BN / 256, 256>>>(salpha, pbs, rs, sbeta, hps);
    k_apply<<<BN, 256>>>(resid, out);
}

// round 4
// speedup vs baseline: 1.5045x; 1.5045x over previous
#include <cuda_runtime.h>
#include <cstdint>

// Problem constants
#define SD    16384          // S*D
#define NJ    22             // 14 alpha cols + 8 beta cols
#define NACC  23             // + sumsq
#define BN    2048           // B*N
#define NCHUNK 2             // k-split (8192 floats each)

typedef unsigned long long ull;

// Scratch (static __device__ arrays; no allocation)
__device__ __align__(16) float g_Wt[NJ * SD];        // Wt[j][k] = (gamma[k]+1)*W[k][j]
__device__ float g_part[NCHUNK][BN][NACC];           // per-chunk partial reductions
__device__ float g_M[BN * 64];                       // per-(b,n) 8x8 mixing matrix

__device__ __forceinline__ void fma2(ull &acc, ull a, ull b) {
    asm("fma.rn.f32x2 %0, %1, %2, %3;" : "=l"(acc) : "l"(a), "l"(b), "l"(acc));
}
__device__ __forceinline__ float f2sum(ull v) {
    float2 f = *reinterpret_cast<float2*>(&v);
    return f.x + f.y;
}
__device__ __forceinline__ float wsum(float v) {
    #pragma unroll
    for (int o = 16; o > 0; o >>= 1) v += __shfl_down_sync(0xffffffffu, v, o);
    return v;
}
__device__ __forceinline__ void cp_async16(uint32_t saddr, const void* gptr) {
    asm volatile("cp.async.cg.shared.global [%0], [%1], 16;\n" :: "r"(saddr), "l"(gptr));
}
__device__ __forceinline__ void cp_commit() {
    asm volatile("cp.async.commit_group;\n");
}

// ---------------------------------------------------------------------------
// Kernel P: build Wt[j][k] = (gamma[k]+1) * W[k][j]  (transposed, gamma-folded)
// ---------------------------------------------------------------------------
__global__ void k_prep(const float* __restrict__ gamma,
                       const float* __restrict__ Wa,
                       const float* __restrict__ Wb) {
    int i = blockIdx.x * blockDim.x + threadIdx.x;
    if (i >= NJ * SD) return;
    int j = i >> 14;          // / 16384
    int k = i & (SD - 1);
    float g = gamma[k] + 1.0f;
    float w = (j < 14) ? Wa[k * 14 + j] : Wb[k * 8 + (j - 14)];
    g_Wt[j * SD + k] = g * w;
}

// ---------------------------------------------------------------------------
// Kernel A: reductions. grid=(64, NCHUNK). Block = 8 warps x 4 bn = 32 bn,
// k-chunk of 8192 floats. Wt staged in smem tiles (256 floats x 22 rows),
// cp.async double-buffered. Each warp reuses each Wt tile across 4 bn.
// ---------------------------------------------------------------------------
#define TKF   256                       // tile width in floats
#define TK16  64                        // tile width in 16B units
#define NTILE 32                        // 8192 / 256
#define TILE_U (NJ * TK16)              // 1408 16B units per tile

__global__ __launch_bounds__(256, 1) void k_reduce(const float* __restrict__ resid) {
    const int tid   = threadIdx.x;
    const int warp  = tid >> 5;
    const int lane  = tid & 31;
    const int chunk = blockIdx.y;

    __shared__ __align__(16) float wts[2][NJ * TKF];   // 2 x 22528 B

    const int bn0 = blockIdx.x * 32 + warp * 4;
    const ulonglong2* r16 = reinterpret_cast<const ulonglong2*>(resid);

    // per-bn base offsets in 16B units: b*4194304 + n*512 (s,d added per tile)
    uint32_t rb[4];
    #pragma unroll
    for (int c = 0; c < 4; c++) {
        int bn = bn0 + c;
        rb[c] = (uint32_t)(bn >> 10) * 4194304u + (uint32_t)(bn & 1023) * 512u;
    }

    ull acc[4][NACC];
    #pragma unroll
    for (int c = 0; c < 4; c++)
        #pragma unroll
        for (int j = 0; j < NACC; j++) acc[c][j] = 0ull;

    const uint32_t sbase0 = (uint32_t)__cvta_generic_to_shared(&wts[0][0]);
    const uint32_t sbase1 = (uint32_t)__cvta_generic_to_shared(&wts[1][0]);
    const float* wsrc = g_Wt + chunk * 8192;

    // --- tile loader: 1408 16B units, 256 threads x up to 6 ---
    auto load_tile = [&](int t, uint32_t sbase) {
        const float* src = wsrc + t * TKF;
        #pragma unroll
        for (int i = 0; i < 6; i++) {
            int u = tid + i * 256;
            if (u < TILE_U) {
                int j = u >> 6, pos = u & 63;       // row, 16B-unit within row
                cp_async16(sbase + u * 16, src + (size_t)j * SD + pos * 4);
            }
        }
        cp_commit();
    };

    load_tile(0, sbase0);

    #pragma unroll 1
    for (int t = 0; t < NTILE; t++) {
        if (t + 1 < NTILE) {
            load_tile(t + 1, ((t + 1) & 1) ? sbase1 : sbase0);
            asm volatile("cp.async.wait_group 1;\n");
        } else {
            asm volatile("cp.async.wait_group 0;\n");
        }
        __syncthreads();

        const ulonglong2* wt16 = reinterpret_cast<const ulonglong2*>(&wts[t & 1][0]);
        // global 16B index for this tile: k16 = chunk*2048 + t*64 + u
        const int k16b = chunk * 2048 + t * 64;
        const int s    = k16b >> 9;
        const uint32_t sadd = (uint32_t)s * 524288u + (uint32_t)(k16b & 511);

        #pragma unroll
        for (int m = 0; m < 2; m++) {
            const int u = m * 32 + lane;
            ulonglong2 rv[4];
            #pragma unroll
            for (int c = 0; c < 4; c++) rv[c] = r16[rb[c] + sadd + u];

            #pragma unroll
            for (int c = 0; c < 4; c++) {
                fma2(acc[c][22], rv[c].x, rv[c].x);
                fma2(acc[c][22], rv[c].y, rv[c].y);
            }
            #pragma unroll
            for (int j = 0; j < NJ; j++) {
                ulonglong2 w = wt16[j * TK16 + u];
                #pragma unroll
                for (int c = 0; c < 4; c++) {
                    fma2(acc[c][j], rv[c].x, w.x);
                    fma2(acc[c][j], rv[c].y, w.y);
                }
            }
        }
        __syncthreads();
    }

    // warp-reduce and store partials
    #pragma unroll
    for (int c = 0; c < 4; c++) {
        int bn = bn0 + c;
        #pragma unroll
        for (int j = 0; j < NACC; j++) {
            float v = wsum(f2sum(acc[c][j]));
            if (lane == 0) g_part[chunk][bn][j] = v;
        }
    }
}

// ---------------------------------------------------------------------------
// Kernel B: per-(b,n) scalar epilogue -> 8x8 mixing matrix M
// ---------------------------------------------------------------------------
__global__ void k_mix(const float* __restrict__ salpha,
                      const float* __restrict__ pbs,
                      const float* __restrict__ rscale,
                      const float* __restrict__ sbeta,
                      const float* __restrict__ hps) {
    int bn = blockIdx.x * blockDim.x + threadIdx.x;
    if (bn >= BN) return;

    float dot[NACC];
    #pragma unroll
    for (int j = 0; j < NACC; j++) {
        float v = 0.0f;
        #pragma unroll
        for (int sp = 0; sp < NCHUNK; sp++) v += g_part[sp][bn][j];
        dot[j] = v;
    }

    float scale = rsqrtf(fmaxf(dot[22], 1e-24f)) * 128.0f;  // sqrt(16384)=128
    float ps = pbs[0], rs = rscale[0], hp = hps[0];

    // w_pre = softmax(ps * dyn_pre + static_alpha[:8])
    float l[8], mx = -1e30f;
    #pragma unroll
    for (int i = 0; i < 8; i++) {
        l[i] = ps * (scale * dot[i]) + salpha[i];
        mx = fmaxf(mx, l[i]);
    }
    float e[8], sum = 0.0f;
    #pragma unroll
    for (int i = 0; i < 8; i++) { e[i] = expf(l[i] - mx); sum += e[i]; }
    float inv_sum = 1.0f / sum;
    float wpre[8];
    #pragma unroll
    for (int i = 0; i < 8; i++) wpre[i] = e[i] * inv_sum;

    // pairwise softmax first elements
    float p[3];
    #pragma unroll
    for (int k = 0; k < 3; k++) {
        float c0 = rs * (scale * dot[8 + 2 * k])     + salpha[8 + 2 * k];
        float c1 = rs * (scale * dot[8 + 2 * k + 1]) + salpha[8 + 2 * k + 1];
        p[k] = 1.0f / (1.0f + expf(c1 - c0));
    }
    // Kron: H[s][t] = h[s^t]
    float h[8];
    #pragma unroll
    for (int x = 0; x < 8; x++) {
        float f0 = (x & 4) ? (1.0f - p[0]) : p[0];
        float f1 = (x & 2) ? (1.0f - p[1]) : p[1];
        float f2 = (x & 1) ? (1.0f - p[2]) : p[2];
        h[x] = f0 * f1 * f2;
    }
    float beta[8];
    #pragma unroll
    for (int t = 0; t < 8; t++)
        beta[t] = 1.0f / (1.0f + expf(-(hp * (scale * dot[14 + t]) + sbeta[t])));

    float* Mo = &g_M[bn * 64];
    #pragma unroll
    for (int s = 0; s < 8; s++)
        #pragma unroll
        for (int t = 0; t < 8; t++)
            Mo[s * 8 + t] = h[s ^ t] + beta[t] * wpre[s];
}

// ---------------------------------------------------------------------------
// Kernel C: out[t,d] = sum_s M[s][t] * r[s,d].  grid=(BN, 2): one CTA per
// (b,n,half-of-D) for more DRAM-level parallelism.
// ---------------------------------------------------------------------------
__global__ __launch_bounds__(256) void k_apply(const float* __restrict__ resid,
                                               float* __restrict__ out) {
    const int bn = blockIdx.x;
    const int b = bn >> 10, n = bn & 1023;

    __shared__ float Ms[64];
    if (threadIdx.x < 64) Ms[threadIdx.x] = g_M[bn * 64 + threadIdx.x];
    __syncthreads();

    float M[64];
    #pragma unroll
    for (int i = 0; i < 64; i++) M[i] = Ms[i];

    const size_t base = (size_t)b * 16777216u + (size_t)n * 2048u;
    const int d = blockIdx.y * 1024 + threadIdx.x * 4;

    float4 acc[8];
    #pragma unroll
    for (int t = 0; t < 8; t++) acc[t] = make_float4(0.f, 0.f, 0.f, 0.f);

    #pragma unroll
    for (int s = 0; s < 8; s++) {
        float4 r4 = *reinterpret_cast<const float4*>(resid + base + (size_t)s * 2097152u + d);
        #pragma unroll
        for (int t = 0; t < 8; t++) {
            float m = M[s * 8 + t];
            acc[t].x += m * r4.x;
            acc[t].y += m * r4.y;
            acc[t].z += m * r4.z;
            acc[t].w += m * r4.w;
        }
    }
    #pragma unroll
    for (int t = 0; t < 8; t++)
        *reinterpret_cast<float4*>(out + base + (size_t)t * 2097152u + d) = acc[t];
}

// ---------------------------------------------------------------------------
extern "C" void kernel_launch(void* const* d_in, const int* in_sizes, int n_in,
                              void* d_out, int out_size) {
    const float* resid  = (const float*)d_in[0];   // residuals (B*S, N, D)
    const float* gamma  = (const float*)d_in[1];   // (S*D,)
    const float* salpha = (const float*)d_in[2];   // (S+T,) = 14
    const float* Wa     = (const float*)d_in[3];   // (S*D, 14)
    const float* pbs    = (const float*)d_in[4];   // (1,)
    const float* rs     = (const float*)d_in[5];   // (1,)
    const float* sbeta  = (const float*)d_in[6];   // (S,) = 8
    const float* Wb     = (const float*)d_in[7];   // (S*D, 8)
    const float* hps    = (const float*)d_in[8];   // scalar
    float* out = (float*)d_out;

    k_prep<<<(NJ * SD + 255) / 256, 256>>>(gamma, Wa, Wb);
    k_reduce<<<dim3(BN / 32, NCHUNK), 256>>>(resid);
    k_mix<<<BN / 256, 256>>>(salpha, pbs, rs, sbeta, hps);
    k_apply<<<dim3(BN, 2), 256>>>(resid, out);
}